// round 14
// baseline (speedup 1.0000x reference)
#include <stdint.h>
#include <cuda_runtime.h>
#include <cuda_bf16.h>
#include <mma.h>
#include <math.h>

using namespace nvcuda;

typedef unsigned int       u32;
typedef unsigned long long u64;

#define B_   2
#define T_   2048
#define D_   1024
#define NH_  16
#define KH_  8
#define H_   128
#define G_   2
#define EPSV 1e-6f
#define LOG_THETA 13.815510557964274f
#define SCALE 0.08838834764831845f
#define KMASK (-3.4028234663852886e38f)

#define M_ (B_*T_)   // 4096

// ---------------- scratch ----------------------------------------------------
__device__ float g_q[M_*NH_*H_];
__device__ float g_k[M_*KH_*H_];
__device__ float g_v[M_*KH_*H_];
__device__ int   g_pos[B_*T_];
// bf16 splits
__device__ __nv_bfloat16 g_x_hi[M_*D_],      g_x_lo[M_*D_];
__device__ __nv_bfloat16 g_qh[M_*NH_*H_],    g_ql[M_*NH_*H_];
__device__ __nv_bfloat16 g_kh[M_*KH_*H_],    g_kl[M_*KH_*H_];
__device__ __nv_bfloat16 g_vh[M_*KH_*H_],    g_vl[M_*KH_*H_];
__device__ __nv_bfloat16 g_oh[M_*NH_*H_],    g_ol[M_*NH_*H_];
__device__ __nv_bfloat16 g_wqt_hi[NH_*H_*D_],g_wqt_lo[NH_*H_*D_];
__device__ __nv_bfloat16 g_wkt_hi[KH_*H_*D_],g_wkt_lo[KH_*H_*D_];
__device__ __nv_bfloat16 g_wvt_hi[KH_*H_*D_],g_wvt_lo[KH_*H_*D_];
__device__ __nv_bfloat16 g_wot_hi[D_*NH_*H_],g_wot_lo[D_*NH_*H_];

// ---------------- fast exp (x <= 0), FFMA-only, rel err ~2e-7 ----------------
__device__ __forceinline__ float fexp(float x) {
    float t = x * 1.4426950408889634f;   // log2(e)
    t = fmaxf(t, -126.0f);
    int ni = __float2int_rn(t);
    float f = t - (float)ni;             // f in [-0.5, 0.5]
    float p = 1.33335581e-3f;
    p = fmaf(p, f, 9.61812911e-3f);
    p = fmaf(p, f, 5.55041087e-2f);
    p = fmaf(p, f, 2.40226507e-1f);
    p = fmaf(p, f, 6.93147180e-1f);
    p = fmaf(p, f, 1.0f);
    return __int_as_float((ni + 127) << 23) * p;
}

// ---------------- positions --------------------------------------------------
__global__ void pos_kernel(const int* __restrict__ seg, int* __restrict__ pos) {
    int b = blockIdx.x;
    const int* s = seg + b * T_;
    __shared__ int red[256];
    int tid = threadIdx.x;
    int lm = -2147483647 - 1;
    for (int t = tid; t < T_; t += 256) lm = max(lm, s[t]);
    red[tid] = lm; __syncthreads();
    for (int o = 128; o > 0; o >>= 1) { if (tid < o) red[tid] = max(red[tid], red[tid+o]); __syncthreads(); }
    int mx = red[0]; __syncthreads();
    int li = T_;
    for (int t = tid; t < T_; t += 256) { if (s[t] == mx) { li = t; break; } }
    red[tid] = li; __syncthreads();
    for (int o = 128; o > 0; o >>= 1) { if (tid < o) red[tid] = min(red[tid], red[tid+o]); __syncthreads(); }
    int off = red[0];
    for (int t = tid; t < T_; t += 256)
        pos[b * T_ + t] = (s[t] != 0) ? (t - off) : (1 << 30);
}

// ---------------- fp32 -> (hi, lo) bf16 split --------------------------------
__device__ __forceinline__ u32 pack_bf16(__nv_bfloat16 a, __nv_bfloat16 b) {
    return ((u32)__bfloat16_as_ushort(b) << 16) | (u32)__bfloat16_as_ushort(a);
}
__global__ void __launch_bounds__(256)
split_kernel(const float* __restrict__ in, __nv_bfloat16* __restrict__ hi,
             __nv_bfloat16* __restrict__ lo, int n) {
    int i = (blockIdx.x * 256 + threadIdx.x) * 4;
    if (i >= n) return;
    float4 x = *(const float4*)(in + i);
    __nv_bfloat16 h0 = __float2bfloat16(x.x), h1 = __float2bfloat16(x.y);
    __nv_bfloat16 h2 = __float2bfloat16(x.z), h3 = __float2bfloat16(x.w);
    __nv_bfloat16 l0 = __float2bfloat16(x.x - __bfloat162float(h0));
    __nv_bfloat16 l1 = __float2bfloat16(x.y - __bfloat162float(h1));
    __nv_bfloat16 l2 = __float2bfloat16(x.z - __bfloat162float(h2));
    __nv_bfloat16 l3 = __float2bfloat16(x.w - __bfloat162float(h3));
    u32* hp = (u32*)(hi + i);
    u32* lp = (u32*)(lo + i);
    hp[0] = pack_bf16(h0, h1); hp[1] = pack_bf16(h2, h3);
    lp[0] = pack_bf16(l0, l1); lp[1] = pack_bf16(l2, l3);
}

// transpose + split: W[Kd][Nc] fp32 -> out[Nc][Kd] bf16 hi/lo
__global__ void __launch_bounds__(256)
tsplit_kernel(const float* __restrict__ W, __nv_bfloat16* __restrict__ hi,
              __nv_bfloat16* __restrict__ lo, int Kd, int Nc) {
    __shared__ float tile[32][33];
    int kx = blockIdx.x * 32, nx = blockIdx.y * 32;
    int tx = threadIdx.x, ty = threadIdx.y;  // 32 x 8
#pragma unroll
    for (int r = 0; r < 32; r += 8)
        tile[ty + r][tx] = W[(size_t)(kx + ty + r) * Nc + nx + tx];
    __syncthreads();
#pragma unroll
    for (int r = 0; r < 32; r += 8) {
        float x = tile[tx][ty + r];
        __nv_bfloat16 h = __float2bfloat16(x);
        __nv_bfloat16 l = __float2bfloat16(x - __bfloat162float(h));
        size_t oi = (size_t)(nx + ty + r) * Kd + kx + tx;
        hi[oi] = h; lo[oi] = l;
    }
}

// ---------------- WMMA bf16 GEMM (3-term split) -------------------------------
#define LDT 40

__global__ void __launch_bounds__(256)
wgemm_kernel(const __nv_bfloat16* __restrict__ Ah, const __nv_bfloat16* __restrict__ Al,
             const __nv_bfloat16* __restrict__ Bh, const __nv_bfloat16* __restrict__ Bl,
             float* __restrict__ C, int M, int Nc, int Kd) {
    __shared__ __nv_bfloat16 sAh[128 * LDT];
    __shared__ __nv_bfloat16 sAl[128 * LDT];
    __shared__ __nv_bfloat16 sBh[128 * LDT];
    __shared__ __nv_bfloat16 sBl[128 * LDT];

    int tid = threadIdx.x;
    int wid = tid >> 5;
    int wm = wid >> 2;
    int wn = wid & 3;
    int bm = blockIdx.y * 128, bn = blockIdx.x * 128;

    int row = tid >> 1;
    int half = (tid & 1) * 16;

    const __nv_bfloat16* pAh = Ah + (size_t)(bm + row) * Kd + half;
    const __nv_bfloat16* pAl = Al + (size_t)(bm + row) * Kd + half;
    const __nv_bfloat16* pBh = Bh + (size_t)(bn + row) * Kd + half;
    const __nv_bfloat16* pBl = Bl + (size_t)(bn + row) * Kd + half;
    __nv_bfloat16* qAh = sAh + row * LDT + half;
    __nv_bfloat16* qAl = sAl + row * LDT + half;
    __nv_bfloat16* qBh = sBh + row * LDT + half;
    __nv_bfloat16* qBl = sBl + row * LDT + half;

    wmma::fragment<wmma::accumulator, 16, 16, 16, float> acc[4][2];
#pragma unroll
    for (int i = 0; i < 4; i++)
#pragma unroll
        for (int j = 0; j < 2; j++)
            wmma::fill_fragment(acc[i][j], 0.0f);

    for (int k0 = 0; k0 < Kd; k0 += 32) {
        *(uint4*)(qAh)     = *(const uint4*)(pAh + k0);
        *(uint4*)(qAh + 8) = *(const uint4*)(pAh + k0 + 8);
        *(uint4*)(qAl)     = *(const uint4*)(pAl + k0);
        *(uint4*)(qAl + 8) = *(const uint4*)(pAl + k0 + 8);
        *(uint4*)(qBh)     = *(const uint4*)(pBh + k0);
        *(uint4*)(qBh + 8) = *(const uint4*)(pBh + k0 + 8);
        *(uint4*)(qBl)     = *(const uint4*)(pBl + k0);
        *(uint4*)(qBl + 8) = *(const uint4*)(pBl + k0 + 8);
        __syncthreads();

#pragma unroll
        for (int kk = 0; kk < 32; kk += 16) {
            wmma::fragment<wmma::matrix_b, 16, 16, 16, __nv_bfloat16, wmma::col_major> fbh[2], fbl[2];
#pragma unroll
            for (int j = 0; j < 2; j++) {
                wmma::load_matrix_sync(fbh[j], sBh + (wn * 32 + j * 16) * LDT + kk, LDT);
                wmma::load_matrix_sync(fbl[j], sBl + (wn * 32 + j * 16) * LDT + kk, LDT);
            }
#pragma unroll
            for (int i = 0; i < 4; i++) {
                wmma::fragment<wmma::matrix_a, 16, 16, 16, __nv_bfloat16, wmma::row_major> fah, fal;
                wmma::load_matrix_sync(fah, sAh + (wm * 64 + i * 16) * LDT + kk, LDT);
                wmma::load_matrix_sync(fal, sAl + (wm * 64 + i * 16) * LDT + kk, LDT);
#pragma unroll
                for (int j = 0; j < 2; j++) {
                    wmma::mma_sync(acc[i][j], fah, fbh[j], acc[i][j]);
                    wmma::mma_sync(acc[i][j], fah, fbl[j], acc[i][j]);
                    wmma::mma_sync(acc[i][j], fal, fbh[j], acc[i][j]);
                }
            }
        }
        __syncthreads();
    }

#pragma unroll
    for (int i = 0; i < 4; i++)
#pragma unroll
        for (int j = 0; j < 2; j++)
            wmma::store_matrix_sync(
                C + (size_t)(bm + wm * 64 + i * 16) * Nc + bn + wn * 32 + j * 16,
                acc[i][j], Nc, wmma::mem_row_major);
}

// ---------------- fused RMSNorm + RoPE -> bf16 hi/lo splits ------------------
// SCALE folded into Q.
__global__ void __launch_bounds__(128)
normrope_kernel(const float* __restrict__ q, const float* __restrict__ k,
                const int* __restrict__ pos,
                const float* __restrict__ qscale, const float* __restrict__ kscale,
                __nv_bfloat16* __restrict__ qh_, __nv_bfloat16* __restrict__ ql_,
                __nv_bfloat16* __restrict__ kh_, __nv_bfloat16* __restrict__ kl_) {
    int gid = blockIdx.x;
    int hh = gid % (NH_ + KH_);
    int bt = gid / (NH_ + KH_);
    int h = threadIdx.x;
    const float* row;
    const float* sc;
    __nv_bfloat16 *oh_, *ol_;
    float fin;
    if (hh < NH_) {
        size_t o = ((size_t)bt * NH_ + hh) * H_;
        row = q + o; sc = qscale; oh_ = qh_ + o; ol_ = ql_ + o; fin = SCALE;
    } else {
        size_t o = ((size_t)bt * KH_ + (hh - NH_)) * H_;
        row = k + o; sc = kscale; oh_ = kh_ + o; ol_ = kl_ + o; fin = 1.0f;
    }
    float v = row[h];
    float ss = v * v;
#pragma unroll
    for (int o = 16; o > 0; o >>= 1) ss += __shfl_xor_sync(0xffffffffu, ss, o);
    __shared__ float wsum[4];
    __shared__ float rbuf[128];
    if ((h & 31) == 0) wsum[h >> 5] = ss;
    __syncthreads();
    float tot = wsum[0] + wsum[1] + wsum[2] + wsum[3];
    float rms = sqrtf(tot * (1.0f / H_) + EPSV);
    rbuf[h] = sc[h] * v / rms;
    __syncthreads();
    if (h < 64) {
        float x1 = rbuf[h], x2 = rbuf[h + 64];
        float inv_freq = expf(-((float)h * (1.0f / 64.0f)) * LOG_THETA);
        float ang = (float)pos[bt] * inv_freq;
        float s, c;
        sincosf(ang, &s, &c);
        float o1 = (x1 * c - x2 * s) * fin;
        float o2 = (x2 * c + x1 * s) * fin;
        __nv_bfloat16 h1 = __float2bfloat16(o1);
        __nv_bfloat16 h2 = __float2bfloat16(o2);
        oh_[h]      = h1; ol_[h]      = __float2bfloat16(o1 - __bfloat162float(h1));
        oh_[h + 64] = h2; ol_[h + 64] = __float2bfloat16(o2 - __bfloat162float(h2));
    }
}

// ---------------- WMMA flash attention ---------------------------------------
// One CTA: (b, head n, 64 q-rows). 256 threads / 8 warps (4x2 warp grid).
#define ALD 136   // bf16/fp32 tile leading dim (128 + 8)
#define SLD 72    // S/P leading dim (64 + 8)
// byte offsets in dynamic smem
#define A_QH 0
#define A_QL (A_QH + 17408)
#define A_KH (A_QL + 17408)
#define A_KL (A_KH + 17408)
#define A_VH (A_KL + 17408)
#define A_VL (A_VH + 17408)
#define A_O  (A_VL + 17408)           // fp32 64 x ALD
#define A_U  (A_O + 34816)            // union: S(18432)+Ph(9216)+Pl(9216); alias O2 (fp32 64xALD)
#define A_MS   (A_U + 36864)
#define A_LS   (A_MS + 256)
#define A_AS   (A_LS + 256)
#define A_POSS (A_AS + 256)
#define A_SEGS (A_POSS + 256)
#define A_POST (A_SEGS + 256)
#define A_SEGT (A_POST + 256)
#define WATTN_SMEM (A_SEGT + 256)     // 177920 bytes

__global__ void __launch_bounds__(256)
wattn_kernel(const __nv_bfloat16* __restrict__ qh, const __nv_bfloat16* __restrict__ ql,
             const __nv_bfloat16* __restrict__ kh, const __nv_bfloat16* __restrict__ kl,
             const __nv_bfloat16* __restrict__ vh, const __nv_bfloat16* __restrict__ vl,
             const int* __restrict__ pos, const int* __restrict__ seg,
             __nv_bfloat16* __restrict__ oh, __nv_bfloat16* __restrict__ ol) {
    extern __shared__ char smc[];
    __nv_bfloat16* sQh = (__nv_bfloat16*)(smc + A_QH);
    __nv_bfloat16* sQl = (__nv_bfloat16*)(smc + A_QL);
    __nv_bfloat16* sKh = (__nv_bfloat16*)(smc + A_KH);
    __nv_bfloat16* sKl = (__nv_bfloat16*)(smc + A_KL);
    __nv_bfloat16* sVh = (__nv_bfloat16*)(smc + A_VH);
    __nv_bfloat16* sVl = (__nv_bfloat16*)(smc + A_VL);
    float* sO  = (float*)(smc + A_O);
    float* sS  = (float*)(smc + A_U);
    __nv_bfloat16* sPh = (__nv_bfloat16*)(smc + A_U + 18432);
    __nv_bfloat16* sPl = (__nv_bfloat16*)(smc + A_U + 27648);
    float* sO2 = (float*)(smc + A_U);
    float* m_s  = (float*)(smc + A_MS);
    float* l_s  = (float*)(smc + A_LS);
    float* al_s = (float*)(smc + A_AS);
    int* poss = (int*)(smc + A_POSS);
    int* segs = (int*)(smc + A_SEGS);
    int* post = (int*)(smc + A_POST);
    int* segt = (int*)(smc + A_SEGT);

    int tid = threadIdx.x, wid = tid >> 5;
    int qt = blockIdx.x, n = blockIdx.y, b = blockIdx.z;
    int kvh = n / G_;
    int wm = wid >> 1, wn = wid & 1;

    // stage Q (64 rows x 128 cols, uint4 = 8 bf16)
    const __nv_bfloat16* qgh = qh + (((size_t)b * T_ + qt * 64) * NH_ + n) * H_;
    const __nv_bfloat16* qgl = ql + (((size_t)b * T_ + qt * 64) * NH_ + n) * H_;
    for (int v = tid; v < 1024; v += 256) {
        int r = v >> 4, c8 = (v & 15) * 8;
        size_t go = (size_t)r * NH_ * H_ + c8;
        *(uint4*)(sQh + r * ALD + c8) = *(const uint4*)(qgh + go);
        *(uint4*)(sQl + r * ALD + c8) = *(const uint4*)(qgl + go);
    }
    if (tid < 64) {
        int t = qt * 64 + tid;
        post[tid] = pos[b * T_ + t];
        segt[tid] = seg[b * T_ + t];
        m_s[tid] = KMASK; l_s[tid] = 0.f;
    }
    for (int i = tid; i < 64 * ALD; i += 256) sO[i] = 0.f;
    __syncthreads();

    for (int st = 0; st <= qt; st++) {
        // stage K, V tiles
        const __nv_bfloat16* kgh = kh + (((size_t)b * T_ + st * 64) * KH_ + kvh) * H_;
        const __nv_bfloat16* kgl = kl + (((size_t)b * T_ + st * 64) * KH_ + kvh) * H_;
        const __nv_bfloat16* vgh = vh + (((size_t)b * T_ + st * 64) * KH_ + kvh) * H_;
        const __nv_bfloat16* vgl = vl + (((size_t)b * T_ + st * 64) * KH_ + kvh) * H_;
        for (int v = tid; v < 1024; v += 256) {
            int r = v >> 4, c8 = (v & 15) * 8;
            size_t go = (size_t)r * KH_ * H_ + c8;
            *(uint4*)(sKh + r * ALD + c8) = *(const uint4*)(kgh + go);
            *(uint4*)(sKl + r * ALD + c8) = *(const uint4*)(kgl + go);
            *(uint4*)(sVh + r * ALD + c8) = *(const uint4*)(vgh + go);
            *(uint4*)(sVl + r * ALD + c8) = *(const uint4*)(vgl + go);
        }
        if (tid < 64) {
            int s = st * 64 + tid;
            poss[tid] = pos[b * T_ + s];
            segs[tid] = seg[b * T_ + s];
        }
        __syncthreads();   // staging done; also: prior-iter O-update done before S overwrites U

        // S = Q K^T : warp tile 16 x 32
        {
            wmma::fragment<wmma::accumulator, 16, 16, 16, float> sa[2];
            wmma::fill_fragment(sa[0], 0.0f);
            wmma::fill_fragment(sa[1], 0.0f);
#pragma unroll
            for (int kk = 0; kk < 128; kk += 16) {
                wmma::fragment<wmma::matrix_a, 16, 16, 16, __nv_bfloat16, wmma::row_major> fah, fal;
                wmma::load_matrix_sync(fah, sQh + (wm * 16) * ALD + kk, ALD);
                wmma::load_matrix_sync(fal, sQl + (wm * 16) * ALD + kk, ALD);
#pragma unroll
                for (int j = 0; j < 2; j++) {
                    wmma::fragment<wmma::matrix_b, 16, 16, 16, __nv_bfloat16, wmma::col_major> fbh, fbl;
                    wmma::load_matrix_sync(fbh, sKh + (wn * 32 + j * 16) * ALD + kk, ALD);
                    wmma::load_matrix_sync(fbl, sKl + (wn * 32 + j * 16) * ALD + kk, ALD);
                    wmma::mma_sync(sa[j], fah, fbh, sa[j]);
                    wmma::mma_sync(sa[j], fah, fbl, sa[j]);
                    wmma::mma_sync(sa[j], fal, fbh, sa[j]);
                }
            }
#pragma unroll
            for (int j = 0; j < 2; j++)
                wmma::store_matrix_sync(sS + (wm * 16) * SLD + wn * 32 + j * 16,
                                        sa[j], SLD, wmma::mem_row_major);
        }
        __syncthreads();

        // masked online softmax (4 threads per row, 16 cols each)
        {
            int r = tid >> 2, q4 = tid & 3, c0 = q4 * 16;
            int pr = post[r], sr = segt[r];
            float s16[16];
            float mx = KMASK;
#pragma unroll
            for (int j = 0; j < 16; j++) {
                int c = c0 + j;
                float s = sS[r * SLD + c];
                bool ok = (poss[c] <= pr) && (segs[c] == sr);
                s = ok ? s : KMASK;
                s16[j] = s;
                mx = fmaxf(mx, s);
            }
            mx = fmaxf(mx, __shfl_xor_sync(0xffffffffu, mx, 1));
            mx = fmaxf(mx, __shfl_xor_sync(0xffffffffu, mx, 2));
            float mo = m_s[r];
            float mn = fmaxf(mo, mx);
            float alpha = fexp(mo - mn);
            float rs = 0.f;
#pragma unroll
            for (int j = 0; j < 16; j++) {
                float p = (s16[j] == KMASK) ? 0.f : fexp(s16[j] - mn);
                __nv_bfloat16 phh = __float2bfloat16(p);
                sPh[r * SLD + c0 + j] = phh;
                sPl[r * SLD + c0 + j] = __float2bfloat16(p - __bfloat162float(phh));
                rs += p;
            }
            rs += __shfl_xor_sync(0xffffffffu, rs, 1);
            rs += __shfl_xor_sync(0xffffffffu, rs, 2);
            if (q4 == 0) { m_s[r] = mn; l_s[r] = l_s[r] * alpha + rs; al_s[r] = alpha; }
        }
        __syncthreads();

        // PV : warp tile 16 x 64
        {
            wmma::fragment<wmma::accumulator, 16, 16, 16, float> oa[4];
#pragma unroll
            for (int j = 0; j < 4; j++) wmma::fill_fragment(oa[j], 0.0f);
#pragma unroll
            for (int ks = 0; ks < 64; ks += 16) {
                wmma::fragment<wmma::matrix_a, 16, 16, 16, __nv_bfloat16, wmma::row_major> fph, fpl;
                wmma::load_matrix_sync(fph, sPh + (wm * 16) * SLD + ks, SLD);
                wmma::load_matrix_sync(fpl, sPl + (wm * 16) * SLD + ks, SLD);
#pragma unroll
                for (int j = 0; j < 4; j++) {
                    wmma::fragment<wmma::matrix_b, 16, 16, 16, __nv_bfloat16, wmma::row_major> fvh, fvl;
                    wmma::load_matrix_sync(fvh, sVh + ks * ALD + wn * 64 + j * 16, ALD);
                    wmma::load_matrix_sync(fvl, sVl + ks * ALD + wn * 64 + j * 16, ALD);
                    wmma::mma_sync(oa[j], fph, fvh, oa[j]);
                    wmma::mma_sync(oa[j], fph, fvl, oa[j]);
                    wmma::mma_sync(oa[j], fpl, fvh, oa[j]);
                }
            }
            __syncthreads();   // all P reads complete before overwriting U
#pragma unroll
            for (int j = 0; j < 4; j++)
                wmma::store_matrix_sync(sO2 + (wm * 16) * ALD + wn * 64 + j * 16,
                                        oa[j], ALD, wmma::mem_row_major);
        }
        __syncthreads();

        // O = O * alpha[r] + PV
        {
            int r = tid >> 2, c0 = (tid & 3) * 32;
            float a = al_s[r];
            float* op = sO + r * ALD + c0;
            float* np = sO2 + r * ALD + c0;
#pragma unroll
            for (int c = 0; c < 32; c += 4) {
                float4 o = *(float4*)(op + c);
                float4 x = *(float4*)(np + c);
                o.x = o.x * a + x.x; o.y = o.y * a + x.y;
                o.z = o.z * a + x.z; o.w = o.w * a + x.w;
                *(float4*)(op + c) = o;
            }
        }
        // loop-top __syncthreads orders this vs next S store
    }
    __syncthreads();

    // epilogue: normalize + bf16 hi/lo split, write to global
    {
        int r = tid >> 2, c0 = (tid & 3) * 32;
        float li = l_s[r];
        if (li <= 0.f) li = 1.f;
        float inv = 1.0f / li;
        size_t gb = (((size_t)b * T_ + qt * 64 + r) * NH_ + n) * H_ + c0;
#pragma unroll
        for (int c = 0; c < 32; c += 2) {
            float v0 = sO[r * ALD + c0 + c] * inv;
            float v1 = sO[r * ALD + c0 + c + 1] * inv;
            __nv_bfloat16 h0 = __float2bfloat16(v0);
            __nv_bfloat16 h1 = __float2bfloat16(v1);
            __nv_bfloat16 l0 = __float2bfloat16(v0 - __bfloat162float(h0));
            __nv_bfloat16 l1 = __float2bfloat16(v1 - __bfloat162float(h1));
            *(u32*)(oh + gb + c) = pack_bf16(h0, h1);
            *(u32*)(ol + gb + c) = pack_bf16(l0, l1);
        }
    }
}

// ---------------- launch ------------------------------------------------------
extern "C" void kernel_launch(void* const* d_in, const int* in_sizes, int n_in,
                              void* d_out, int out_size) {
    const float* x   = (const float*)d_in[0];
    const int*   seg = (const int*)  d_in[1];
    const float* wq  = (const float*)d_in[2];
    const float* wk  = (const float*)d_in[3];
    const float* wv  = (const float*)d_in[4];
    const float* wo  = (const float*)d_in[5];
    const float* qsc = (const float*)d_in[6];
    const float* ksc = (const float*)d_in[7];
    float* out = (float*)d_out;

    float *q, *k, *v;
    int* pos;
    __nv_bfloat16 *xh, *xl, *qh, *ql, *kh, *kl, *vh, *vl, *oh, *ol;
    __nv_bfloat16 *wqh, *wql, *wkh, *wkl, *wvh, *wvl, *woh, *wol;
    cudaGetSymbolAddress((void**)&q,   g_q);
    cudaGetSymbolAddress((void**)&k,   g_k);
    cudaGetSymbolAddress((void**)&v,   g_v);
    cudaGetSymbolAddress((void**)&pos, g_pos);
    cudaGetSymbolAddress((void**)&xh,  g_x_hi);  cudaGetSymbolAddress((void**)&xl,  g_x_lo);
    cudaGetSymbolAddress((void**)&qh,  g_qh);    cudaGetSymbolAddress((void**)&ql,  g_ql);
    cudaGetSymbolAddress((void**)&kh,  g_kh);    cudaGetSymbolAddress((void**)&kl,  g_kl);
    cudaGetSymbolAddress((void**)&vh,  g_vh);    cudaGetSymbolAddress((void**)&vl,  g_vl);
    cudaGetSymbolAddress((void**)&oh,  g_oh);    cudaGetSymbolAddress((void**)&ol,  g_ol);
    cudaGetSymbolAddress((void**)&wqh, g_wqt_hi); cudaGetSymbolAddress((void**)&wql, g_wqt_lo);
    cudaGetSymbolAddress((void**)&wkh, g_wkt_hi); cudaGetSymbolAddress((void**)&wkl, g_wkt_lo);
    cudaGetSymbolAddress((void**)&wvh, g_wvt_hi); cudaGetSymbolAddress((void**)&wvl, g_wvt_lo);
    cudaGetSymbolAddress((void**)&woh, g_wot_hi); cudaGetSymbolAddress((void**)&wol, g_wot_lo);

    cudaFuncSetAttribute(wattn_kernel, cudaFuncAttributeMaxDynamicSharedMemorySize, WATTN_SMEM);

    pos_kernel<<<B_, 256>>>(seg, pos);

    // splits / transposes
    split_kernel<<<(M_*D_/4 + 255)/256, 256>>>(x, xh, xl, M_*D_);
    dim3 tb(32, 8);
    tsplit_kernel<<<dim3(D_/32, (NH_*H_)/32), tb>>>(wq, wqh, wql, D_, NH_*H_);
    tsplit_kernel<<<dim3(D_/32, (KH_*H_)/32), tb>>>(wk, wkh, wkl, D_, KH_*H_);
    tsplit_kernel<<<dim3(D_/32, (KH_*H_)/32), tb>>>(wv, wvh, wvl, D_, KH_*H_);
    tsplit_kernel<<<dim3((NH_*H_)/32, D_/32), tb>>>(wo, woh, wol, NH_*H_, D_);

    // projections on tensor cores (WMMA/HMMA)
    wgemm_kernel<<<dim3((NH_*H_)/128, M_/128), 256>>>(xh, xl, wqh, wql, q, M_, NH_*H_, D_);
    wgemm_kernel<<<dim3((KH_*H_)/128, M_/128), 256>>>(xh, xl, wkh, wkl, k, M_, KH_*H_, D_);
    wgemm_kernel<<<dim3((KH_*H_)/128, M_/128), 256>>>(xh, xl, wvh, wvl, v, M_, KH_*H_, D_);

    // norm + rope -> q/k bf16 splits; v element-wise split
    normrope_kernel<<<M_ * (NH_ + KH_), 128>>>(q, k, pos, qsc, ksc, qh, ql, kh, kl);
    split_kernel<<<(M_*KH_*H_/4 + 255)/256, 256>>>(v, vh, vl, M_*KH_*H_);

    // WMMA flash attention -> o bf16 splits
    wattn_kernel<<<dim3(T_/64, NH_, B_), 256, WATTN_SMEM>>>(qh, ql, kh, kl, vh, vl, pos, seg, oh, ol);

    // output projection
    wgemm_kernel<<<dim3(D_/128, M_/128), 256>>>(oh, ol, woh, wol, out, M_, D_, NH_*H_);
}

// round 15
// speedup vs baseline: 1.1337x; 1.1337x over previous
#include <stdint.h>
#include <cuda_runtime.h>
#include <cuda_bf16.h>
#include <mma.h>
#include <math.h>

using namespace nvcuda;

typedef unsigned int       u32;
typedef unsigned long long u64;

#define B_   2
#define T_   2048
#define D_   1024
#define NH_  16
#define KH_  8
#define H_   128
#define G_   2
#define EPSV 1e-6f
#define LOG_THETA 13.815510557964274f
#define SCALE 0.08838834764831845f
#define KMASK (-3.4028234663852886e38f)

#define M_ (B_*T_)   // 4096

// ---------------- scratch ----------------------------------------------------
__device__ float g_q[M_*NH_*H_];
__device__ float g_k[M_*KH_*H_];
__device__ float g_v[M_*KH_*H_];
__device__ float g_o[M_*NH_*H_];
__device__ int   g_pos[B_*T_];
// bf16 splits
__device__ __nv_bfloat16 g_x_hi[M_*D_],      g_x_lo[M_*D_];
__device__ __nv_bfloat16 g_o_hi[M_*NH_*H_],  g_o_lo[M_*NH_*H_];
__device__ __nv_bfloat16 g_wqt_hi[NH_*H_*D_],g_wqt_lo[NH_*H_*D_];
__device__ __nv_bfloat16 g_wkt_hi[KH_*H_*D_],g_wkt_lo[KH_*H_*D_];
__device__ __nv_bfloat16 g_wvt_hi[KH_*H_*D_],g_wvt_lo[KH_*H_*D_];
__device__ __nv_bfloat16 g_wot_hi[D_*NH_*H_],g_wot_lo[D_*NH_*H_];

// ---------------- fast exp (x <= 0), FFMA-only, rel err ~2e-7 ----------------
__device__ __forceinline__ float fexp(float x) {
    float t = x * 1.4426950408889634f;   // log2(e)
    t = fmaxf(t, -126.0f);
    int ni = __float2int_rn(t);
    float f = t - (float)ni;             // f in [-0.5, 0.5]
    float p = 1.33335581e-3f;
    p = fmaf(p, f, 9.61812911e-3f);
    p = fmaf(p, f, 5.55041087e-2f);
    p = fmaf(p, f, 2.40226507e-1f);
    p = fmaf(p, f, 6.93147180e-1f);
    p = fmaf(p, f, 1.0f);
    return __int_as_float((ni + 127) << 23) * p;
}

// ---------------- positions --------------------------------------------------
__global__ void pos_kernel(const int* __restrict__ seg, int* __restrict__ pos) {
    int b = blockIdx.x;
    const int* s = seg + b * T_;
    __shared__ int red[256];
    int tid = threadIdx.x;
    int lm = -2147483647 - 1;
    for (int t = tid; t < T_; t += 256) lm = max(lm, s[t]);
    red[tid] = lm; __syncthreads();
    for (int o = 128; o > 0; o >>= 1) { if (tid < o) red[tid] = max(red[tid], red[tid+o]); __syncthreads(); }
    int mx = red[0]; __syncthreads();
    int li = T_;
    for (int t = tid; t < T_; t += 256) { if (s[t] == mx) { li = t; break; } }
    red[tid] = li; __syncthreads();
    for (int o = 128; o > 0; o >>= 1) { if (tid < o) red[tid] = min(red[tid], red[tid+o]); __syncthreads(); }
    int off = red[0];
    for (int t = tid; t < T_; t += 256)
        pos[b * T_ + t] = (s[t] != 0) ? (t - off) : (1 << 30);
}

// ---------------- fp32 -> (hi, lo) bf16 split --------------------------------
__device__ __forceinline__ u32 pack_bf16(__nv_bfloat16 a, __nv_bfloat16 b) {
    return ((u32)__bfloat16_as_ushort(b) << 16) | (u32)__bfloat16_as_ushort(a);
}
__global__ void __launch_bounds__(256)
split_kernel(const float* __restrict__ in, __nv_bfloat16* __restrict__ hi,
             __nv_bfloat16* __restrict__ lo, int n) {
    int i = (blockIdx.x * 256 + threadIdx.x) * 4;
    if (i >= n) return;
    float4 x = *(const float4*)(in + i);
    __nv_bfloat16 h0 = __float2bfloat16(x.x), h1 = __float2bfloat16(x.y);
    __nv_bfloat16 h2 = __float2bfloat16(x.z), h3 = __float2bfloat16(x.w);
    __nv_bfloat16 l0 = __float2bfloat16(x.x - __bfloat162float(h0));
    __nv_bfloat16 l1 = __float2bfloat16(x.y - __bfloat162float(h1));
    __nv_bfloat16 l2 = __float2bfloat16(x.z - __bfloat162float(h2));
    __nv_bfloat16 l3 = __float2bfloat16(x.w - __bfloat162float(h3));
    u32* hp = (u32*)(hi + i);
    u32* lp = (u32*)(lo + i);
    hp[0] = pack_bf16(h0, h1); hp[1] = pack_bf16(h2, h3);
    lp[0] = pack_bf16(l0, l1); lp[1] = pack_bf16(l2, l3);
}

// transpose + split: W[Kd][Nc] fp32 -> out[Nc][Kd] bf16 hi/lo
__global__ void __launch_bounds__(256)
tsplit_kernel(const float* __restrict__ W, __nv_bfloat16* __restrict__ hi,
              __nv_bfloat16* __restrict__ lo, int Kd, int Nc) {
    __shared__ float tile[32][33];
    int kx = blockIdx.x * 32, nx = blockIdx.y * 32;
    int tx = threadIdx.x, ty = threadIdx.y;  // 32 x 8
#pragma unroll
    for (int r = 0; r < 32; r += 8)
        tile[ty + r][tx] = W[(size_t)(kx + ty + r) * Nc + nx + tx];
    __syncthreads();
#pragma unroll
    for (int r = 0; r < 32; r += 8) {
        float x = tile[tx][ty + r];
        __nv_bfloat16 h = __float2bfloat16(x);
        __nv_bfloat16 l = __float2bfloat16(x - __bfloat162float(h));
        size_t oi = (size_t)(nx + ty + r) * Kd + kx + tx;
        hi[oi] = h; lo[oi] = l;
    }
}

// ---------------- WMMA bf16 GEMM (3-term split) -------------------------------
#define LDT 40

__global__ void __launch_bounds__(256)
wgemm_kernel(const __nv_bfloat16* __restrict__ Ah, const __nv_bfloat16* __restrict__ Al,
             const __nv_bfloat16* __restrict__ Bh, const __nv_bfloat16* __restrict__ Bl,
             float* __restrict__ C, int M, int Nc, int Kd) {
    __shared__ __nv_bfloat16 sAh[128 * LDT];
    __shared__ __nv_bfloat16 sAl[128 * LDT];
    __shared__ __nv_bfloat16 sBh[128 * LDT];
    __shared__ __nv_bfloat16 sBl[128 * LDT];

    int tid = threadIdx.x;
    int wid = tid >> 5;
    int wm = wid >> 2;
    int wn = wid & 3;
    int bm = blockIdx.y * 128, bn = blockIdx.x * 128;

    int row = tid >> 1;
    int half = (tid & 1) * 16;

    const __nv_bfloat16* pAh = Ah + (size_t)(bm + row) * Kd + half;
    const __nv_bfloat16* pAl = Al + (size_t)(bm + row) * Kd + half;
    const __nv_bfloat16* pBh = Bh + (size_t)(bn + row) * Kd + half;
    const __nv_bfloat16* pBl = Bl + (size_t)(bn + row) * Kd + half;
    __nv_bfloat16* qAh = sAh + row * LDT + half;
    __nv_bfloat16* qAl = sAl + row * LDT + half;
    __nv_bfloat16* qBh = sBh + row * LDT + half;
    __nv_bfloat16* qBl = sBl + row * LDT + half;

    wmma::fragment<wmma::accumulator, 16, 16, 16, float> acc[4][2];
#pragma unroll
    for (int i = 0; i < 4; i++)
#pragma unroll
        for (int j = 0; j < 2; j++)
            wmma::fill_fragment(acc[i][j], 0.0f);

    for (int k0 = 0; k0 < Kd; k0 += 32) {
        *(uint4*)(qAh)     = *(const uint4*)(pAh + k0);
        *(uint4*)(qAh + 8) = *(const uint4*)(pAh + k0 + 8);
        *(uint4*)(qAl)     = *(const uint4*)(pAl + k0);
        *(uint4*)(qAl + 8) = *(const uint4*)(pAl + k0 + 8);
        *(uint4*)(qBh)     = *(const uint4*)(pBh + k0);
        *(uint4*)(qBh + 8) = *(const uint4*)(pBh + k0 + 8);
        *(uint4*)(qBl)     = *(const uint4*)(pBl + k0);
        *(uint4*)(qBl + 8) = *(const uint4*)(pBl + k0 + 8);
        __syncthreads();

#pragma unroll
        for (int kk = 0; kk < 32; kk += 16) {
            wmma::fragment<wmma::matrix_b, 16, 16, 16, __nv_bfloat16, wmma::col_major> fbh[2], fbl[2];
#pragma unroll
            for (int j = 0; j < 2; j++) {
                wmma::load_matrix_sync(fbh[j], sBh + (wn * 32 + j * 16) * LDT + kk, LDT);
                wmma::load_matrix_sync(fbl[j], sBl + (wn * 32 + j * 16) * LDT + kk, LDT);
            }
#pragma unroll
            for (int i = 0; i < 4; i++) {
                wmma::fragment<wmma::matrix_a, 16, 16, 16, __nv_bfloat16, wmma::row_major> fah, fal;
                wmma::load_matrix_sync(fah, sAh + (wm * 64 + i * 16) * LDT + kk, LDT);
                wmma::load_matrix_sync(fal, sAl + (wm * 64 + i * 16) * LDT + kk, LDT);
#pragma unroll
                for (int j = 0; j < 2; j++) {
                    wmma::mma_sync(acc[i][j], fah, fbh[j], acc[i][j]);
                    wmma::mma_sync(acc[i][j], fah, fbl[j], acc[i][j]);
                    wmma::mma_sync(acc[i][j], fal, fbh[j], acc[i][j]);
                }
            }
        }
        __syncthreads();
    }

#pragma unroll
    for (int i = 0; i < 4; i++)
#pragma unroll
        for (int j = 0; j < 2; j++)
            wmma::store_matrix_sync(
                C + (size_t)(bm + wm * 64 + i * 16) * Nc + bn + wn * 32 + j * 16,
                acc[i][j], Nc, wmma::mem_row_major);
}

// ---------------- fused RMSNorm + RoPE ---------------------------------------
__global__ void __launch_bounds__(128)
normrope_kernel(float* __restrict__ q, float* __restrict__ k,
                const int* __restrict__ pos,
                const float* __restrict__ qscale, const float* __restrict__ kscale) {
    int gid = blockIdx.x;
    int hh = gid % (NH_ + KH_);
    int bt = gid / (NH_ + KH_);
    int h = threadIdx.x;
    float* row;
    const float* sc;
    if (hh < NH_) { row = q + ((size_t)bt * NH_ + hh) * H_;         sc = qscale; }
    else          { row = k + ((size_t)bt * KH_ + (hh - NH_)) * H_; sc = kscale; }
    float v = row[h];
    float ss = v * v;
#pragma unroll
    for (int o = 16; o > 0; o >>= 1) ss += __shfl_xor_sync(0xffffffffu, ss, o);
    __shared__ float wsum[4];
    __shared__ float rbuf[128];
    if ((h & 31) == 0) wsum[h >> 5] = ss;
    __syncthreads();
    float tot = wsum[0] + wsum[1] + wsum[2] + wsum[3];
    float rms = sqrtf(tot * (1.0f / H_) + EPSV);
    rbuf[h] = sc[h] * v / rms;
    __syncthreads();
    if (h < 64) {
        float x1 = rbuf[h], x2 = rbuf[h + 64];
        float inv_freq = expf(-((float)h * (1.0f / 64.0f)) * LOG_THETA);
        float ang = (float)pos[bt] * inv_freq;
        float s, c;
        sincosf(ang, &s, &c);
        row[h]      = x1 * c - x2 * s;
        row[h + 64] = x2 * c + x1 * s;
    }
}

// ---------------- flash-style causal GQA attention (SIMT, fp32, poly-exp) ----
#define BQ 64
#define BS 64
#define ATTN_SMEM ((64*129 + 64*129 + 64*128 + 64*65) * 4 + 64*2*4)

__global__ void __launch_bounds__(256)
attn_kernel(const float* __restrict__ q, const float* __restrict__ k,
            const float* __restrict__ v, const int* __restrict__ pos,
            const int* __restrict__ seg, float* __restrict__ o) {
    extern __shared__ float sm[];
    float* qs = sm;
    float* ks = qs + 64 * 129;
    float* vs = ks + 64 * 129;
    float* ps = vs + 64 * 128;
    int* poss = (int*)(ps + 64 * 65);
    int* segs = poss + 64;

    int tid = threadIdx.x;
    int qt = blockIdx.x, n = blockIdx.y, b = blockIdx.z;
    int kvh = n / G_;
    int ty = tid >> 4, tx = tid & 15;
    int r0 = ty * 4;

    const float* qg = q + (((size_t)b * T_ + qt * BQ) * NH_ + n) * H_;
    for (int idx = tid; idx < BQ * H_; idx += 256) {
        int r = idx >> 7, h = idx & 127;
        qs[r * 129 + h] = qg[(size_t)r * NH_ * H_ + h] * SCALE;
    }
    int post[4], segt[4];
#pragma unroll
    for (int i = 0; i < 4; i++) {
        int t = qt * BQ + r0 + i;
        post[i] = pos[b * T_ + t];
        segt[i] = seg[b * T_ + t];
    }
    float m[4], l[4], acc[4][8];
#pragma unroll
    for (int i = 0; i < 4; i++) {
        m[i] = KMASK; l[i] = 0.f;
#pragma unroll
        for (int j = 0; j < 8; j++) acc[i][j] = 0.f;
    }

    int nst = qt + 1;
    for (int st = 0; st < nst; st++) {
        __syncthreads();
        const float* kg = k + (((size_t)b * T_ + st * BS) * KH_ + kvh) * H_;
        const float* vg = v + (((size_t)b * T_ + st * BS) * KH_ + kvh) * H_;
        for (int idx = tid; idx < BS * H_; idx += 256) {
            int r = idx >> 7, h = idx & 127;
            ks[r * 129 + h] = kg[(size_t)r * KH_ * H_ + h];
            vs[r * 128 + h] = vg[(size_t)r * KH_ * H_ + h];
        }
        if (tid < BS) {
            int s = st * BS + tid;
            poss[tid] = pos[b * T_ + s];
            segs[tid] = seg[b * T_ + s];
        }
        __syncthreads();

        float s4[4][4];
#pragma unroll
        for (int i = 0; i < 4; i++)
#pragma unroll
            for (int j = 0; j < 4; j++) s4[i][j] = 0.f;
#pragma unroll 4
        for (int h = 0; h < H_; h++) {
            float a0 = qs[(r0 + 0) * 129 + h];
            float a1 = qs[(r0 + 1) * 129 + h];
            float a2 = qs[(r0 + 2) * 129 + h];
            float a3 = qs[(r0 + 3) * 129 + h];
            float b0 = ks[(tx * 4 + 0) * 129 + h];
            float b1 = ks[(tx * 4 + 1) * 129 + h];
            float b2 = ks[(tx * 4 + 2) * 129 + h];
            float b3 = ks[(tx * 4 + 3) * 129 + h];
            s4[0][0] = fmaf(a0, b0, s4[0][0]); s4[0][1] = fmaf(a0, b1, s4[0][1]);
            s4[0][2] = fmaf(a0, b2, s4[0][2]); s4[0][3] = fmaf(a0, b3, s4[0][3]);
            s4[1][0] = fmaf(a1, b0, s4[1][0]); s4[1][1] = fmaf(a1, b1, s4[1][1]);
            s4[1][2] = fmaf(a1, b2, s4[1][2]); s4[1][3] = fmaf(a1, b3, s4[1][3]);
            s4[2][0] = fmaf(a2, b0, s4[2][0]); s4[2][1] = fmaf(a2, b1, s4[2][1]);
            s4[2][2] = fmaf(a2, b2, s4[2][2]); s4[2][3] = fmaf(a2, b3, s4[2][3]);
            s4[3][0] = fmaf(a3, b0, s4[3][0]); s4[3][1] = fmaf(a3, b1, s4[3][1]);
            s4[3][2] = fmaf(a3, b2, s4[3][2]); s4[3][3] = fmaf(a3, b3, s4[3][3]);
        }

#pragma unroll
        for (int i = 0; i < 4; i++) {
            float tm = KMASK;
#pragma unroll
            for (int j = 0; j < 4; j++) {
                int c = tx * 4 + j;
                bool ok = (poss[c] <= post[i]) && (segs[c] == segt[i]);
                if (!ok) s4[i][j] = KMASK;
                tm = fmaxf(tm, s4[i][j]);
            }
#pragma unroll
            for (int ofs = 8; ofs > 0; ofs >>= 1)
                tm = fmaxf(tm, __shfl_xor_sync(0xffffffffu, tm, ofs));
            float mn = fmaxf(m[i], tm);
            float alpha = fexp(m[i] - mn);
            float rs = 0.f;
#pragma unroll
            for (int j = 0; j < 4; j++) {
                float p = (s4[i][j] == KMASK) ? 0.f : fexp(s4[i][j] - mn);
                ps[(r0 + i) * 65 + tx * 4 + j] = p;
                rs += p;
            }
#pragma unroll
            for (int ofs = 8; ofs > 0; ofs >>= 1)
                rs += __shfl_xor_sync(0xffffffffu, rs, ofs);
            l[i] = l[i] * alpha + rs;
            m[i] = mn;
#pragma unroll
            for (int j = 0; j < 8; j++) acc[i][j] *= alpha;
        }
        __syncwarp();

#pragma unroll 2
        for (int kk = 0; kk < BS; kk++) {
            float p0 = ps[(r0 + 0) * 65 + kk];
            float p1 = ps[(r0 + 1) * 65 + kk];
            float p2 = ps[(r0 + 2) * 65 + kk];
            float p3 = ps[(r0 + 3) * 65 + kk];
            float4 v0 = *(const float4*)&vs[kk * 128 + tx * 8];
            float4 v1 = *(const float4*)&vs[kk * 128 + tx * 8 + 4];
            float vv[8] = {v0.x, v0.y, v0.z, v0.w, v1.x, v1.y, v1.z, v1.w};
#pragma unroll
            for (int j = 0; j < 8; j++) {
                acc[0][j] = fmaf(p0, vv[j], acc[0][j]);
                acc[1][j] = fmaf(p1, vv[j], acc[1][j]);
                acc[2][j] = fmaf(p2, vv[j], acc[2][j]);
                acc[3][j] = fmaf(p3, vv[j], acc[3][j]);
            }
        }
    }

#pragma unroll
    for (int i = 0; i < 4; i++) {
        float li = l[i];
        if (li <= 0.f) li = 1.f;
        float inv = 1.0f / li;
        float4 c0 = make_float4(acc[i][0]*inv, acc[i][1]*inv, acc[i][2]*inv, acc[i][3]*inv);
        float4 c1 = make_float4(acc[i][4]*inv, acc[i][5]*inv, acc[i][6]*inv, acc[i][7]*inv);
        float* op = o + (((size_t)b * T_ + qt * BQ + r0 + i) * NH_ + n) * H_ + tx * 8;
        *(float4*)op = c0;
        *(float4*)(op + 4) = c1;
    }
}

// ---------------- launch ------------------------------------------------------
extern "C" void kernel_launch(void* const* d_in, const int* in_sizes, int n_in,
                              void* d_out, int out_size) {
    const float* x   = (const float*)d_in[0];
    const int*   seg = (const int*)  d_in[1];
    const float* wq  = (const float*)d_in[2];
    const float* wk  = (const float*)d_in[3];
    const float* wv  = (const float*)d_in[4];
    const float* wo  = (const float*)d_in[5];
    const float* qsc = (const float*)d_in[6];
    const float* ksc = (const float*)d_in[7];
    float* out = (float*)d_out;

    float *q, *k, *v, *o;
    int* pos;
    __nv_bfloat16 *xh, *xl, *oh, *ol, *wqh, *wql, *wkh, *wkl, *wvh, *wvl, *woh, *wol;
    cudaGetSymbolAddress((void**)&q,   g_q);
    cudaGetSymbolAddress((void**)&k,   g_k);
    cudaGetSymbolAddress((void**)&v,   g_v);
    cudaGetSymbolAddress((void**)&o,   g_o);
    cudaGetSymbolAddress((void**)&pos, g_pos);
    cudaGetSymbolAddress((void**)&xh,  g_x_hi);  cudaGetSymbolAddress((void**)&xl,  g_x_lo);
    cudaGetSymbolAddress((void**)&oh,  g_o_hi);  cudaGetSymbolAddress((void**)&ol,  g_o_lo);
    cudaGetSymbolAddress((void**)&wqh, g_wqt_hi); cudaGetSymbolAddress((void**)&wql, g_wqt_lo);
    cudaGetSymbolAddress((void**)&wkh, g_wkt_hi); cudaGetSymbolAddress((void**)&wkl, g_wkt_lo);
    cudaGetSymbolAddress((void**)&wvh, g_wvt_hi); cudaGetSymbolAddress((void**)&wvl, g_wvt_lo);
    cudaGetSymbolAddress((void**)&woh, g_wot_hi); cudaGetSymbolAddress((void**)&wol, g_wot_lo);

    cudaFuncSetAttribute(attn_kernel, cudaFuncAttributeMaxDynamicSharedMemorySize, ATTN_SMEM);

    pos_kernel<<<B_, 256>>>(seg, pos);

    // splits / transposes
    split_kernel<<<(M_*D_/4 + 255)/256, 256>>>(x, xh, xl, M_*D_);
    dim3 tb(32, 8);
    tsplit_kernel<<<dim3(D_/32, (NH_*H_)/32), tb>>>(wq, wqh, wql, D_, NH_*H_);
    tsplit_kernel<<<dim3(D_/32, (KH_*H_)/32), tb>>>(wk, wkh, wkl, D_, KH_*H_);
    tsplit_kernel<<<dim3(D_/32, (KH_*H_)/32), tb>>>(wv, wvh, wvl, D_, KH_*H_);
    tsplit_kernel<<<dim3((NH_*H_)/32, D_/32), tb>>>(wo, woh, wol, NH_*H_, D_);

    // projections on tensor cores (WMMA/HMMA)
    wgemm_kernel<<<dim3((NH_*H_)/128, M_/128), 256>>>(xh, xl, wqh, wql, q, M_, NH_*H_, D_);
    wgemm_kernel<<<dim3((KH_*H_)/128, M_/128), 256>>>(xh, xl, wkh, wkl, k, M_, KH_*H_, D_);
    wgemm_kernel<<<dim3((KH_*H_)/128, M_/128), 256>>>(xh, xl, wvh, wvl, v, M_, KH_*H_, D_);

    normrope_kernel<<<M_ * (NH_ + KH_), 128>>>(q, k, pos, qsc, ksc);

    attn_kernel<<<dim3(T_/BQ, NH_, B_), 256, ATTN_SMEM>>>(q, k, v, pos, seg, o);

    split_kernel<<<(M_*NH_*H_/4 + 255)/256, 256>>>(o, oh, ol, M_*NH_*H_);
    wgemm_kernel<<<dim3(D_/128, M_/128), 256>>>(oh, ol, woh, wol, out, M_, D_, NH_*H_);
}

// round 16
// speedup vs baseline: 1.2973x; 1.1443x over previous
#include <stdint.h>
#include <cuda_runtime.h>
#include <cuda_bf16.h>
#include <mma.h>
#include <math.h>

using namespace nvcuda;

typedef unsigned int       u32;
typedef unsigned long long u64;

#define B_   2
#define T_   2048
#define D_   1024
#define NH_  16
#define KH_  8
#define H_   128
#define G_   2
#define EPSV 1e-6f
#define LOG_THETA 13.815510557964274f
#define SCALE 0.08838834764831845f
#define KMASK (-3.4028234663852886e38f)

#define M_ (B_*T_)   // 4096

// ---------------- scratch ----------------------------------------------------
__device__ float g_q[M_*NH_*H_];
__device__ float g_k[M_*KH_*H_];
__device__ float g_v[M_*KH_*H_];
__device__ int   g_pos[B_*T_];
// bf16 splits
__device__ __nv_bfloat16 g_x_hi[M_*D_],      g_x_lo[M_*D_];
__device__ __nv_bfloat16 g_o_hi[M_*NH_*H_],  g_o_lo[M_*NH_*H_];
__device__ __nv_bfloat16 g_wqt_hi[NH_*H_*D_],g_wqt_lo[NH_*H_*D_];
__device__ __nv_bfloat16 g_wkt_hi[KH_*H_*D_],g_wkt_lo[KH_*H_*D_];
__device__ __nv_bfloat16 g_wvt_hi[KH_*H_*D_],g_wvt_lo[KH_*H_*D_];
__device__ __nv_bfloat16 g_wot_hi[D_*NH_*H_],g_wot_lo[D_*NH_*H_];

// ---------------- fast exp (x <= 0), FFMA-only, rel err ~2e-7 ----------------
__device__ __forceinline__ float fexp(float x) {
    float t = x * 1.4426950408889634f;   // log2(e)
    t = fmaxf(t, -126.0f);
    int ni = __float2int_rn(t);
    float f = t - (float)ni;             // f in [-0.5, 0.5]
    float p = 1.33335581e-3f;
    p = fmaf(p, f, 9.61812911e-3f);
    p = fmaf(p, f, 5.55041087e-2f);
    p = fmaf(p, f, 2.40226507e-1f);
    p = fmaf(p, f, 6.93147180e-1f);
    p = fmaf(p, f, 1.0f);
    return __int_as_float((ni + 127) << 23) * p;
}

// ---------------- positions --------------------------------------------------
__global__ void pos_kernel(const int* __restrict__ seg, int* __restrict__ pos) {
    int b = blockIdx.x;
    const int* s = seg + b * T_;
    __shared__ int red[256];
    int tid = threadIdx.x;
    int lm = -2147483647 - 1;
    for (int t = tid; t < T_; t += 256) lm = max(lm, s[t]);
    red[tid] = lm; __syncthreads();
    for (int o = 128; o > 0; o >>= 1) { if (tid < o) red[tid] = max(red[tid], red[tid+o]); __syncthreads(); }
    int mx = red[0]; __syncthreads();
    int li = T_;
    for (int t = tid; t < T_; t += 256) { if (s[t] == mx) { li = t; break; } }
    red[tid] = li; __syncthreads();
    for (int o = 128; o > 0; o >>= 1) { if (tid < o) red[tid] = min(red[tid], red[tid+o]); __syncthreads(); }
    int off = red[0];
    for (int t = tid; t < T_; t += 256)
        pos[b * T_ + t] = (s[t] != 0) ? (t - off) : (1 << 30);
}

// ---------------- fp32 -> (hi, lo) bf16 split --------------------------------
__device__ __forceinline__ u32 pack_bf16(__nv_bfloat16 a, __nv_bfloat16 b) {
    return ((u32)__bfloat16_as_ushort(b) << 16) | (u32)__bfloat16_as_ushort(a);
}
__global__ void __launch_bounds__(256)
split_kernel(const float* __restrict__ in, __nv_bfloat16* __restrict__ hi,
             __nv_bfloat16* __restrict__ lo, int n) {
    int i = (blockIdx.x * 256 + threadIdx.x) * 4;
    if (i >= n) return;
    float4 x = *(const float4*)(in + i);
    __nv_bfloat16 h0 = __float2bfloat16(x.x), h1 = __float2bfloat16(x.y);
    __nv_bfloat16 h2 = __float2bfloat16(x.z), h3 = __float2bfloat16(x.w);
    __nv_bfloat16 l0 = __float2bfloat16(x.x - __bfloat162float(h0));
    __nv_bfloat16 l1 = __float2bfloat16(x.y - __bfloat162float(h1));
    __nv_bfloat16 l2 = __float2bfloat16(x.z - __bfloat162float(h2));
    __nv_bfloat16 l3 = __float2bfloat16(x.w - __bfloat162float(h3));
    u32* hp = (u32*)(hi + i);
    u32* lp = (u32*)(lo + i);
    hp[0] = pack_bf16(h0, h1); hp[1] = pack_bf16(h2, h3);
    lp[0] = pack_bf16(l0, l1); lp[1] = pack_bf16(l2, l3);
}

// transpose + split: W[Kd][Nc] fp32 -> out[Nc][Kd] bf16 hi/lo
__global__ void __launch_bounds__(256)
tsplit_kernel(const float* __restrict__ W, __nv_bfloat16* __restrict__ hi,
              __nv_bfloat16* __restrict__ lo, int Kd, int Nc) {
    __shared__ float tile[32][33];
    int kx = blockIdx.x * 32, nx = blockIdx.y * 32;
    int tx = threadIdx.x, ty = threadIdx.y;  // 32 x 8
#pragma unroll
    for (int r = 0; r < 32; r += 8)
        tile[ty + r][tx] = W[(size_t)(kx + ty + r) * Nc + nx + tx];
    __syncthreads();
#pragma unroll
    for (int r = 0; r < 32; r += 8) {
        float x = tile[tx][ty + r];
        __nv_bfloat16 h = __float2bfloat16(x);
        __nv_bfloat16 l = __float2bfloat16(x - __bfloat162float(h));
        size_t oi = (size_t)(nx + ty + r) * Kd + kx + tx;
        hi[oi] = h; lo[oi] = l;
    }
}

// ---------------- WMMA bf16 GEMM (3-term split) -------------------------------
#define LDT 40

__global__ void __launch_bounds__(256)
wgemm_kernel(const __nv_bfloat16* __restrict__ Ah, const __nv_bfloat16* __restrict__ Al,
             const __nv_bfloat16* __restrict__ Bh, const __nv_bfloat16* __restrict__ Bl,
             float* __restrict__ C, int M, int Nc, int Kd) {
    __shared__ __nv_bfloat16 sAh[128 * LDT];
    __shared__ __nv_bfloat16 sAl[128 * LDT];
    __shared__ __nv_bfloat16 sBh[128 * LDT];
    __shared__ __nv_bfloat16 sBl[128 * LDT];

    int tid = threadIdx.x;
    int wid = tid >> 5;
    int wm = wid >> 2;
    int wn = wid & 3;
    int bm = blockIdx.y * 128, bn = blockIdx.x * 128;

    int row = tid >> 1;
    int half = (tid & 1) * 16;

    const __nv_bfloat16* pAh = Ah + (size_t)(bm + row) * Kd + half;
    const __nv_bfloat16* pAl = Al + (size_t)(bm + row) * Kd + half;
    const __nv_bfloat16* pBh = Bh + (size_t)(bn + row) * Kd + half;
    const __nv_bfloat16* pBl = Bl + (size_t)(bn + row) * Kd + half;
    __nv_bfloat16* qAh = sAh + row * LDT + half;
    __nv_bfloat16* qAl = sAl + row * LDT + half;
    __nv_bfloat16* qBh = sBh + row * LDT + half;
    __nv_bfloat16* qBl = sBl + row * LDT + half;

    wmma::fragment<wmma::accumulator, 16, 16, 16, float> acc[4][2];
#pragma unroll
    for (int i = 0; i < 4; i++)
#pragma unroll
        for (int j = 0; j < 2; j++)
            wmma::fill_fragment(acc[i][j], 0.0f);

    for (int k0 = 0; k0 < Kd; k0 += 32) {
        *(uint4*)(qAh)     = *(const uint4*)(pAh + k0);
        *(uint4*)(qAh + 8) = *(const uint4*)(pAh + k0 + 8);
        *(uint4*)(qAl)     = *(const uint4*)(pAl + k0);
        *(uint4*)(qAl + 8) = *(const uint4*)(pAl + k0 + 8);
        *(uint4*)(qBh)     = *(const uint4*)(pBh + k0);
        *(uint4*)(qBh + 8) = *(const uint4*)(pBh + k0 + 8);
        *(uint4*)(qBl)     = *(const uint4*)(pBl + k0);
        *(uint4*)(qBl + 8) = *(const uint4*)(pBl + k0 + 8);
        __syncthreads();

#pragma unroll
        for (int kk = 0; kk < 32; kk += 16) {
            wmma::fragment<wmma::matrix_b, 16, 16, 16, __nv_bfloat16, wmma::col_major> fbh[2], fbl[2];
#pragma unroll
            for (int j = 0; j < 2; j++) {
                wmma::load_matrix_sync(fbh[j], sBh + (wn * 32 + j * 16) * LDT + kk, LDT);
                wmma::load_matrix_sync(fbl[j], sBl + (wn * 32 + j * 16) * LDT + kk, LDT);
            }
#pragma unroll
            for (int i = 0; i < 4; i++) {
                wmma::fragment<wmma::matrix_a, 16, 16, 16, __nv_bfloat16, wmma::row_major> fah, fal;
                wmma::load_matrix_sync(fah, sAh + (wm * 64 + i * 16) * LDT + kk, LDT);
                wmma::load_matrix_sync(fal, sAl + (wm * 64 + i * 16) * LDT + kk, LDT);
#pragma unroll
                for (int j = 0; j < 2; j++) {
                    wmma::mma_sync(acc[i][j], fah, fbh[j], acc[i][j]);
                    wmma::mma_sync(acc[i][j], fah, fbl[j], acc[i][j]);
                    wmma::mma_sync(acc[i][j], fal, fbh[j], acc[i][j]);
                }
            }
        }
        __syncthreads();
    }

#pragma unroll
    for (int i = 0; i < 4; i++)
#pragma unroll
        for (int j = 0; j < 2; j++)
            wmma::store_matrix_sync(
                C + (size_t)(bm + wm * 64 + i * 16) * Nc + bn + wn * 32 + j * 16,
                acc[i][j], Nc, wmma::mem_row_major);
}

// ---------------- fused RMSNorm + RoPE ---------------------------------------
__global__ void __launch_bounds__(128)
normrope_kernel(float* __restrict__ q, float* __restrict__ k,
                const int* __restrict__ pos,
                const float* __restrict__ qscale, const float* __restrict__ kscale) {
    int gid = blockIdx.x;
    int hh = gid % (NH_ + KH_);
    int bt = gid / (NH_ + KH_);
    int h = threadIdx.x;
    float* row;
    const float* sc;
    if (hh < NH_) { row = q + ((size_t)bt * NH_ + hh) * H_;         sc = qscale; }
    else          { row = k + ((size_t)bt * KH_ + (hh - NH_)) * H_; sc = kscale; }
    float v = row[h];
    float ss = v * v;
#pragma unroll
    for (int o = 16; o > 0; o >>= 1) ss += __shfl_xor_sync(0xffffffffu, ss, o);
    __shared__ float wsum[4];
    __shared__ float rbuf[128];
    if ((h & 31) == 0) wsum[h >> 5] = ss;
    __syncthreads();
    float tot = wsum[0] + wsum[1] + wsum[2] + wsum[3];
    float rms = sqrtf(tot * (1.0f / H_) + EPSV);
    rbuf[h] = sc[h] * v / rms;
    __syncthreads();
    if (h < 64) {
        float x1 = rbuf[h], x2 = rbuf[h + 64];
        float inv_freq = expf(-((float)h * (1.0f / 64.0f)) * LOG_THETA);
        float ang = (float)pos[bt] * inv_freq;
        float s, c;
        sincosf(ang, &s, &c);
        row[h]      = x1 * c - x2 * s;
        row[h + 64] = x2 * c + x1 * s;
    }
}

// ---------------- flash attention: vectorized SIMT, swizzled layouts ----------
// Layouts: qs_t/ks_t transposed [h][r], stride 64, XOR granule swizzle;
// ps_t transposed [kk][r], same swizzle; vs row-major [kk][h] stride 128.
#define SWZ(maj, mn) ((maj) * 64 + ((mn) ^ ((((maj) >> 2) & 15) << 2)))
#define OFF_K  8192
#define OFF_V  16384
#define OFF_P  24576
#define OFF_I  28672
#define ATTN_SMEM (28672*4 + 512)

__global__ void __launch_bounds__(256)
attn_kernel(const float* __restrict__ q, const float* __restrict__ k,
            const float* __restrict__ v, const int* __restrict__ pos,
            const int* __restrict__ seg,
            __nv_bfloat16* __restrict__ ohp, __nv_bfloat16* __restrict__ olp) {
    extern __shared__ float sm[];
    float* qs_t = sm;
    float* ks_t = sm + OFF_K;
    float* vs   = sm + OFF_V;
    float* ps_t = sm + OFF_P;
    int* poss = (int*)(sm + OFF_I);
    int* segs = poss + 64;

    int tid = threadIdx.x;
    int qt = blockIdx.x, n = blockIdx.y, b = blockIdx.z;
    int kvh = n / G_;
    int ty = tid >> 4, tx = tid & 15;
    int r0 = ty * 4, c0 = tx * 4;

    // stage Q transposed+swizzled (scaled)
    const float* qg = q + (((size_t)b * T_ + qt * 64) * NH_ + n) * H_;
    for (int idx = tid; idx < 2048; idx += 256) {
        int r = idx >> 5, h4 = (idx & 31) * 4;
        float4 t = *(const float4*)(qg + (size_t)r * NH_ * H_ + h4);
        qs_t[SWZ(h4 + 0, r)] = t.x * SCALE;
        qs_t[SWZ(h4 + 1, r)] = t.y * SCALE;
        qs_t[SWZ(h4 + 2, r)] = t.z * SCALE;
        qs_t[SWZ(h4 + 3, r)] = t.w * SCALE;
    }
    int post[4], segt[4];
#pragma unroll
    for (int i = 0; i < 4; i++) {
        int t = qt * 64 + r0 + i;
        post[i] = pos[b * T_ + t];
        segt[i] = seg[b * T_ + t];
    }
    float m[4], l[4], acc[4][8];
#pragma unroll
    for (int i = 0; i < 4; i++) {
        m[i] = KMASK; l[i] = 0.f;
#pragma unroll
        for (int j = 0; j < 8; j++) acc[i][j] = 0.f;
    }

    for (int st = 0; st <= qt; st++) {
        __syncthreads();
        const float* kg = k + (((size_t)b * T_ + st * 64) * KH_ + kvh) * H_;
        const float* vg = v + (((size_t)b * T_ + st * 64) * KH_ + kvh) * H_;
        for (int idx = tid; idx < 2048; idx += 256) {
            int r = idx >> 5, h4 = (idx & 31) * 4;
            size_t go = (size_t)r * KH_ * H_ + h4;
            float4 kt = *(const float4*)(kg + go);
            ks_t[SWZ(h4 + 0, r)] = kt.x;
            ks_t[SWZ(h4 + 1, r)] = kt.y;
            ks_t[SWZ(h4 + 2, r)] = kt.z;
            ks_t[SWZ(h4 + 3, r)] = kt.w;
            *(float4*)(vs + r * 128 + h4) = *(const float4*)(vg + go);
        }
        if (tid < 64) {
            int s = st * 64 + tid;
            poss[tid] = pos[b * T_ + s];
            segs[tid] = seg[b * T_ + s];
        }
        __syncthreads();

        // S = Q K^T : per thread 4x4, float4 LDS both sides
        float s4[4][4];
#pragma unroll
        for (int i = 0; i < 4; i++)
#pragma unroll
            for (int j = 0; j < 4; j++) s4[i][j] = 0.f;
#pragma unroll 4
        for (int h = 0; h < H_; h++) {
            float4 qv = *(const float4*)&qs_t[SWZ(h, r0)];
            float4 kv = *(const float4*)&ks_t[SWZ(h, c0)];
            s4[0][0] = fmaf(qv.x, kv.x, s4[0][0]); s4[0][1] = fmaf(qv.x, kv.y, s4[0][1]);
            s4[0][2] = fmaf(qv.x, kv.z, s4[0][2]); s4[0][3] = fmaf(qv.x, kv.w, s4[0][3]);
            s4[1][0] = fmaf(qv.y, kv.x, s4[1][0]); s4[1][1] = fmaf(qv.y, kv.y, s4[1][1]);
            s4[1][2] = fmaf(qv.y, kv.z, s4[1][2]); s4[1][3] = fmaf(qv.y, kv.w, s4[1][3]);
            s4[2][0] = fmaf(qv.z, kv.x, s4[2][0]); s4[2][1] = fmaf(qv.z, kv.y, s4[2][1]);
            s4[2][2] = fmaf(qv.z, kv.z, s4[2][2]); s4[2][3] = fmaf(qv.z, kv.w, s4[2][3]);
            s4[3][0] = fmaf(qv.w, kv.x, s4[3][0]); s4[3][1] = fmaf(qv.w, kv.y, s4[3][1]);
            s4[3][2] = fmaf(qv.w, kv.z, s4[3][2]); s4[3][3] = fmaf(qv.w, kv.w, s4[3][3]);
        }

        // masked online softmax; write P transposed+swizzled
#pragma unroll
        for (int i = 0; i < 4; i++) {
            float tm = KMASK;
#pragma unroll
            for (int j = 0; j < 4; j++) {
                int c = c0 + j;
                bool ok = (poss[c] <= post[i]) && (segs[c] == segt[i]);
                if (!ok) s4[i][j] = KMASK;
                tm = fmaxf(tm, s4[i][j]);
            }
#pragma unroll
            for (int ofs = 8; ofs > 0; ofs >>= 1)
                tm = fmaxf(tm, __shfl_xor_sync(0xffffffffu, tm, ofs));
            float mn = fmaxf(m[i], tm);
            float alpha = fexp(m[i] - mn);
            float rs = 0.f;
#pragma unroll
            for (int j = 0; j < 4; j++) {
                float p = (s4[i][j] == KMASK) ? 0.f : fexp(s4[i][j] - mn);
                ps_t[SWZ(c0 + j, r0 + i)] = p;
                rs += p;
            }
#pragma unroll
            for (int ofs = 8; ofs > 0; ofs >>= 1)
                rs += __shfl_xor_sync(0xffffffffu, rs, ofs);
            l[i] = l[i] * alpha + rs;
            m[i] = mn;
#pragma unroll
            for (int j = 0; j < 8; j++) acc[i][j] *= alpha;
        }
        __syncwarp();   // P producers/consumers for rows r0..r0+3 are in-warp

        // O += P V : per kk one float4 p-load + two float4 v-loads
#pragma unroll 2
        for (int kk = 0; kk < 64; kk++) {
            float4 p4 = *(const float4*)&ps_t[SWZ(kk, r0)];
            float4 v0 = *(const float4*)&vs[kk * 128 + tx * 8];
            float4 v1 = *(const float4*)&vs[kk * 128 + tx * 8 + 4];
            float vv[8] = {v0.x, v0.y, v0.z, v0.w, v1.x, v1.y, v1.z, v1.w};
#pragma unroll
            for (int j = 0; j < 8; j++) {
                acc[0][j] = fmaf(p4.x, vv[j], acc[0][j]);
                acc[1][j] = fmaf(p4.y, vv[j], acc[1][j]);
                acc[2][j] = fmaf(p4.z, vv[j], acc[2][j]);
                acc[3][j] = fmaf(p4.w, vv[j], acc[3][j]);
            }
        }
    }

    // epilogue: normalize + bf16 hi/lo split, direct global write
#pragma unroll
    for (int i = 0; i < 4; i++) {
        float li = l[i];
        if (li <= 0.f) li = 1.f;
        float inv = 1.0f / li;
        size_t gb = (((size_t)b * T_ + qt * 64 + r0 + i) * NH_ + n) * H_ + tx * 8;
        u32 hw[4], lw[4];
#pragma unroll
        for (int j = 0; j < 4; j++) {
            float v0 = acc[i][j * 2]     * inv;
            float v1 = acc[i][j * 2 + 1] * inv;
            __nv_bfloat16 h0 = __float2bfloat16(v0);
            __nv_bfloat16 h1 = __float2bfloat16(v1);
            __nv_bfloat16 l0 = __float2bfloat16(v0 - __bfloat162float(h0));
            __nv_bfloat16 l1 = __float2bfloat16(v1 - __bfloat162float(h1));
            hw[j] = pack_bf16(h0, h1);
            lw[j] = pack_bf16(l0, l1);
        }
        *(uint4*)(ohp + gb) = make_uint4(hw[0], hw[1], hw[2], hw[3]);
        *(uint4*)(olp + gb) = make_uint4(lw[0], lw[1], lw[2], lw[3]);
    }
}

// ---------------- launch ------------------------------------------------------
extern "C" void kernel_launch(void* const* d_in, const int* in_sizes, int n_in,
                              void* d_out, int out_size) {
    const float* x   = (const float*)d_in[0];
    const int*   seg = (const int*)  d_in[1];
    const float* wq  = (const float*)d_in[2];
    const float* wk  = (const float*)d_in[3];
    const float* wv  = (const float*)d_in[4];
    const float* wo  = (const float*)d_in[5];
    const float* qsc = (const float*)d_in[6];
    const float* ksc = (const float*)d_in[7];
    float* out = (float*)d_out;

    float *q, *k, *v;
    int* pos;
    __nv_bfloat16 *xh, *xl, *oh, *ol, *wqh, *wql, *wkh, *wkl, *wvh, *wvl, *woh, *wol;
    cudaGetSymbolAddress((void**)&q,   g_q);
    cudaGetSymbolAddress((void**)&k,   g_k);
    cudaGetSymbolAddress((void**)&v,   g_v);
    cudaGetSymbolAddress((void**)&pos, g_pos);
    cudaGetSymbolAddress((void**)&xh,  g_x_hi);  cudaGetSymbolAddress((void**)&xl,  g_x_lo);
    cudaGetSymbolAddress((void**)&oh,  g_o_hi);  cudaGetSymbolAddress((void**)&ol,  g_o_lo);
    cudaGetSymbolAddress((void**)&wqh, g_wqt_hi); cudaGetSymbolAddress((void**)&wql, g_wqt_lo);
    cudaGetSymbolAddress((void**)&wkh, g_wkt_hi); cudaGetSymbolAddress((void**)&wkl, g_wkt_lo);
    cudaGetSymbolAddress((void**)&wvh, g_wvt_hi); cudaGetSymbolAddress((void**)&wvl, g_wvt_lo);
    cudaGetSymbolAddress((void**)&woh, g_wot_hi); cudaGetSymbolAddress((void**)&wol, g_wot_lo);

    cudaFuncSetAttribute(attn_kernel, cudaFuncAttributeMaxDynamicSharedMemorySize, ATTN_SMEM);

    pos_kernel<<<B_, 256>>>(seg, pos);

    // splits / transposes
    split_kernel<<<(M_*D_/4 + 255)/256, 256>>>(x, xh, xl, M_*D_);
    dim3 tb(32, 8);
    tsplit_kernel<<<dim3(D_/32, (NH_*H_)/32), tb>>>(wq, wqh, wql, D_, NH_*H_);
    tsplit_kernel<<<dim3(D_/32, (KH_*H_)/32), tb>>>(wk, wkh, wkl, D_, KH_*H_);
    tsplit_kernel<<<dim3(D_/32, (KH_*H_)/32), tb>>>(wv, wvh, wvl, D_, KH_*H_);
    tsplit_kernel<<<dim3((NH_*H_)/32, D_/32), tb>>>(wo, woh, wol, NH_*H_, D_);

    // projections on tensor cores (WMMA/HMMA)
    wgemm_kernel<<<dim3((NH_*H_)/128, M_/128), 256>>>(xh, xl, wqh, wql, q, M_, NH_*H_, D_);
    wgemm_kernel<<<dim3((KH_*H_)/128, M_/128), 256>>>(xh, xl, wkh, wkl, k, M_, KH_*H_, D_);
    wgemm_kernel<<<dim3((KH_*H_)/128, M_/128), 256>>>(xh, xl, wvh, wvl, v, M_, KH_*H_, D_);

    normrope_kernel<<<M_ * (NH_ + KH_), 128>>>(q, k, pos, qsc, ksc);

    // attention writes o hi/lo splits directly
    attn_kernel<<<dim3(T_/64, NH_, B_), 256, ATTN_SMEM>>>(q, k, v, pos, seg, oh, ol);

    // output projection
    wgemm_kernel<<<dim3(D_/128, M_/128), 256>>>(oh, ol, woh, wol, out, M_, D_, NH_*H_);
}